// round 16
// baseline (speedup 1.0000x reference)
#include <cuda_runtime.h>
#include <cuda_bf16.h>
#include <cstdint>
#include <stdint.h>
#include <math.h>

#define VV 16000
#define BB 8
#define TT 1024
#define DD 64
#define FF 256
#define EE 8
#define BT (BB*TT)

// ---------------- device scratch (no allocations allowed) ----------------
__device__ float g_emb[BT*DD];        // 2 MB   embedded tokens (fp32, residual path)
__device__ float g_A[BT*DD];          // 2 MB   x_t @ Wm + bm
__device__ float g_mem[BT*DD];        // 2 MB   recurrent state per step
__device__ float g_eo[BT*EE*DD];      // 16.8 MB per-expert FFN outputs (pre-gate)
__device__ __nv_bfloat16 g_embh[BT*DD];   // 1 MB  emb bf16 (FFN input)
__device__ __nv_bfloat16 g_outh[BT*DD];   // 1 MB  LN output, bf16 hi
__device__ __nv_bfloat16 g_outl[BT*DD];   // 1 MB  LN output, bf16 lo (residual)
__device__ __nv_bfloat16 g_hWh[VV*DD];    // 2 MB  head_W^T [n][k] bf16 hi
__device__ __nv_bfloat16 g_hWl[VV*DD];    // 2 MB  head_W^T [n][k] bf16 lo
__device__ __nv_bfloat16 g_W1t[EE*FF*DD]; // 256KB W1^T [e][f][k] bf16
__device__ __nv_bfloat16 g_W2t[EE*DD*FF]; // 256KB W2^T [e][d][f] bf16

typedef unsigned long long ull;

__device__ __forceinline__ float tanh_fast(float x){
    float r; asm("tanh.approx.f32 %0, %1;" : "=f"(r) : "f"(x)); return r;
}
__device__ __forceinline__ unsigned bf2(float lo, float hi){
    unsigned r; asm("cvt.rn.bf16x2.f32 %0, %1, %2;" : "=r"(r) : "f"(hi), "f"(lo)); return r;
}
__device__ __forceinline__ uint32_t smem_u32(const void* p){
    uint32_t a; asm("{ .reg .u64 t; cvta.to.shared.u64 t, %1; cvt.u32.u64 %0, t; }" : "=r"(a) : "l"(p));
    return a;
}
__device__ __forceinline__ void cpa16(uint32_t s, const void* g){
    asm volatile("cp.async.cg.shared.global [%0], [%1], 16;" :: "r"(s), "l"(g));
}
__device__ __forceinline__ void cpa_commit(){ asm volatile("cp.async.commit_group;"); }
__device__ __forceinline__ void cpa_wait1(){ asm volatile("cp.async.wait_group 1;"); }
__device__ __forceinline__ void cpa_wait0(){ asm volatile("cp.async.wait_group 0;"); }

__device__ __forceinline__ void ldm4(uint32_t a[4], uint32_t addr){
    asm volatile("ldmatrix.sync.aligned.m8n8.x4.shared.b16 {%0,%1,%2,%3}, [%4];"
                 : "=r"(a[0]), "=r"(a[1]), "=r"(a[2]), "=r"(a[3]) : "r"(addr));
}
__device__ __forceinline__ void mma16816(float d[4], const uint32_t a[4], const uint32_t b[2]){
    asm volatile("mma.sync.aligned.m16n8k16.row.col.f32.bf16.bf16.f32 "
                 "{%0,%1,%2,%3}, {%4,%5,%6,%7}, {%8,%9}, {%0,%1,%2,%3};"
                 : "+f"(d[0]), "+f"(d[1]), "+f"(d[2]), "+f"(d[3])
                 : "r"(a[0]), "r"(a[1]), "r"(a[2]), "r"(a[3]), "r"(b[0]), "r"(b[1]));
}

// ---------------- K0a: head_W -> transposed bf16 hi/lo ----------------
__global__ __launch_bounds__(256) void k_cvt_w(const float* __restrict__ hW)
{
    __shared__ float tile[64][132];
    int n0 = blockIdx.x * 128;
    int tid = threadIdx.x;
    for (int idx = tid; idx < 64*128; idx += 256){
        int k = idx >> 7, n = idx & 127;
        tile[k][n] = hW[(size_t)k*VV + n0 + n];
    }
    __syncthreads();
    int r = tid >> 1, k0 = (tid & 1) * 32;
    unsigned hw[16], lw[16];
#pragma unroll
    for (int q = 0; q < 16; q++){
        float a = tile[k0 + 2*q][r], b = tile[k0 + 2*q + 1][r];
        float ha = __bfloat162float(__float2bfloat16(a));
        float hb = __bfloat162float(__float2bfloat16(b));
        hw[q] = bf2(ha, hb);
        lw[q] = bf2(a - ha, b - hb);
    }
    uint4* dh = (uint4*)(g_hWh + (size_t)(n0 + r)*DD + k0);
    uint4* dl = (uint4*)(g_hWl + (size_t)(n0 + r)*DD + k0);
#pragma unroll
    for (int j = 0; j < 4; j++){ dh[j] = ((uint4*)hw)[j]; dl[j] = ((uint4*)lw)[j]; }
}

// ---------------- K0b: W1/W2 -> transposed bf16 ----------------
__global__ __launch_bounds__(256) void k_cvt_ffn(const float* __restrict__ W1,
                                                 const float* __restrict__ W2)
{
    __shared__ float t[8320];           // max(32*260, 64*68)
    int e = blockIdx.x;
    int tid = threadIdx.x;
    if (blockIdx.y == 0){
        // W1[e] [64 k][256 f] -> g_W1t[e][f][k]
        for (int c = 0; c < 2; c++){
            __syncthreads();
            for (int i = tid; i < 32*256; i += 256){
                int kk = i >> 8, f = i & 255;
                t[kk*260 + f] = W1[((size_t)e*64 + c*32 + kk)*256 + f];
            }
            __syncthreads();
            int f = tid;
            unsigned w[16];
#pragma unroll
            for (int q = 0; q < 16; q++)
                w[q] = bf2(t[(2*q)*260 + f], t[(2*q+1)*260 + f]);
            uint4* dst = (uint4*)(g_W1t + ((size_t)e*256 + f)*64 + c*32);
#pragma unroll
            for (int j = 0; j < 4; j++) dst[j] = ((uint4*)w)[j];
        }
    } else {
        // W2[e] [256 f][64 d] -> g_W2t[e][d][f]
        for (int c = 0; c < 4; c++){
            __syncthreads();
            for (int i = tid; i < 64*64; i += 256){
                int ff = i >> 6, d = i & 63;
                t[ff*68 + d] = W2[((size_t)e*256 + c*64 + ff)*64 + d];
            }
            __syncthreads();
            int d = tid >> 2, sub = tid & 3;
            unsigned w[8];
#pragma unroll
            for (int q = 0; q < 8; q++)
                w[q] = bf2(t[(sub*16 + 2*q)*68 + d], t[(sub*16 + 2*q + 1)*68 + d]);
            uint4* dst = (uint4*)(g_W2t + ((size_t)e*64 + d)*256 + c*64 + sub*16);
#pragma unroll
            for (int j = 0; j < 2; j++) dst[j] = ((uint4*)w)[j];
        }
    }
}

// ---------------- K1: embedding gather + A = emb @ Wm + bm ----------------
__global__ void k_embA(const int* __restrict__ x, const float* __restrict__ tab,
                       const float* __restrict__ Wm, const float* __restrict__ bm)
{
    int bt = blockIdx.x;
    int d  = threadIdx.x;
    __shared__ __align__(16) float xs[DD];
    float v = tab[x[bt]*DD + d];
    xs[d] = v;
    g_emb[bt*DD + d] = v;
    g_embh[bt*DD + d] = __float2bfloat16(v);
    __syncthreads();
    float acc = bm[d];
    const float4* xr = (const float4*)xs;
#pragma unroll
    for (int k4 = 0; k4 < 16; k4++){
        float4 m4 = xr[k4];
        acc += m4.x*Wm[(k4*4+0)*DD+d] + m4.y*Wm[(k4*4+1)*DD+d]
             + m4.z*Wm[(k4*4+2)*DD+d] + m4.w*Wm[(k4*4+3)*DD+d];
    }
    g_A[bt*DD + d] = acc;
}

// ---------------- K2: recurrence (blocks 0..7) || HMMA FFN (blocks 8..) ----------------
// FFN smem layout (dynamic):
#define FSX   0                        // X  [64 m][72 bf16]  (144 B rows)
#define FSW1  9216                     // W1t [256 f][72 bf16]
#define FSH   46080                    // H  [64 m][264 bf16] (528 B rows)
#define FSW2  79872                    // W2t [64 d][264 bf16]
#define FTOT  113664

__global__ __launch_bounds__(256) void k_main(
    const float* __restrict__ Um,
    const float* __restrict__ b1, const float* __restrict__ b2)
{
    extern __shared__ char smem[];
    if (blockIdx.x < BB) {
        // -------- low-latency recurrence: quad-per-d, shfl reduce, 1 bar/step --------
        float* buf0 = (float*)smem;            // [64]
        float* buf1 = buf0 + 64;               // [64]
        int b   = blockIdx.x;
        int tid = threadIdx.x;
        int q = tid & 3, d = tid >> 2;         // 4 k-partials of one d in adjacent lanes
        float um[16];
#pragma unroll
        for (int j = 0; j < 16; j++) um[j] = Um[(q*16 + j)*DD + d];
        if (q == 0){ buf0[d] = 0.f; }
        __syncthreads();
        const float* Ab = g_A  + b*TT*DD;
        float*       Mb = g_mem + b*TT*DD;
        float a_cur = Ab[d];
        float a_nx  = Ab[DD + d];
        float* smcur = buf0;
        float* smnxt = buf1;
        for (int t = 0; t < TT; t++){
            float a_pf = 0.f;
            if (t + 2 < TT) a_pf = Ab[(t+2)*DD + d];      // 2-step prefetch (L2 latency)
            const float4* mv = (const float4*)(smcur + q*16);
            float4 m0 = mv[0], m1 = mv[1], m2 = mv[2], m3 = mv[3];
            // 4 independent FMA chains (latency 16 instead of 64)
            float p0 = m0.x*um[0]  + m0.y*um[1]  + m0.z*um[2]  + m0.w*um[3];
            float p1 = m1.x*um[4]  + m1.y*um[5]  + m1.z*um[6]  + m1.w*um[7];
            float p2 = m2.x*um[8]  + m2.y*um[9]  + m2.z*um[10] + m2.w*um[11];
            float p3 = m3.x*um[12] + m3.y*um[13] + m3.z*um[14] + m3.w*um[15];
            float p  = (p0 + p1) + (p2 + p3);
            p += __shfl_xor_sync(0xffffffffu, p, 1);
            p += __shfl_xor_sync(0xffffffffu, p, 2);
            float m = tanh_fast(a_cur + p);
            if (q == 0){
                smnxt[d]    = m;
                Mb[t*DD + d] = m;
            }
            a_cur = a_nx; a_nx = a_pf;
            __syncthreads();                   // single barrier per step
            float* tmp = smcur; smcur = smnxt; smnxt = tmp;
        }
    } else {
        uint32_t sbm = smem_u32(smem);
        int idx = blockIdx.x - BB;
        int e = idx & 7, tok0 = (idx >> 3) * 64;
        int tid = threadIdx.x;
        int wid = tid >> 5, lane = tid & 31;

        // ---- async loads: X, W1t, W2t ----
        {
            int row = tid >> 2, q = tid & 3;   // X: 64 rows x 128B
            const char* src = (const char*)(g_embh + (size_t)(tok0 + row)*DD) + q*32;
            uint32_t dst = sbm + FSX + row*144 + q*32;
            cpa16(dst, src); cpa16(dst + 16, src + 16);
        }
        {
            int row = tid;                     // W1t: 256 rows x 128B
            const char* src = (const char*)(g_W1t + ((size_t)e*256 + row)*64);
            uint32_t dst = sbm + FSW1 + row*144;
#pragma unroll
            for (int j = 0; j < 8; j++) cpa16(dst + j*16, src + j*16);
        }
        {
            int row = tid >> 2, q = tid & 3;   // W2t: 64 rows x 512B
            const char* src = (const char*)(g_W2t + ((size_t)e*64 + row)*256) + q*128;
            uint32_t dst = sbm + FSW2 + row*528 + q*128;
#pragma unroll
            for (int j = 0; j < 8; j++) cpa16(dst + j*16, src + j*16);
        }
        cpa_commit();
        cpa_wait0();
        __syncthreads();

        int g = lane >> 2, tig = lane & 3;
        int lr = lane & 7, sel = lane >> 3;
        int aoffX = (lr + (sel & 1)*8)*144 + ((sel >> 1)*8)*2;
        int aoffH = (lr + (sel & 1)*8)*528 + ((sel >> 1)*8)*2;

        // ---- GEMM1: H = gelu(X @ W1t^T + b1) ; warp grid 4(M) x 2(N), tile 16x128 ----
        {
            int mw = wid & 3, nw = wid >> 2;
            float d1[16][4];
#pragma unroll
            for (int nt = 0; nt < 16; nt++)
#pragma unroll
                for (int q = 0; q < 4; q++) d1[nt][q] = 0.f;
#pragma unroll
            for (int kt = 0; kt < 4; kt++){
                uint32_t a[4];
                ldm4(a, sbm + FSX + (mw*16)*144 + kt*32 + aoffX);
#pragma unroll
                for (int nt = 0; nt < 16; nt++){
                    int brow = nw*128 + nt*8 + g;
                    uint32_t b[2];
                    b[0] = *(const uint32_t*)(smem + FSW1 + brow*144 + kt*32 + tig*4);
                    b[1] = *(const uint32_t*)(smem + FSW1 + brow*144 + kt*32 + tig*4 + 16);
                    mma16816(d1[nt], a, b);
                }
            }
            int r0 = mw*16 + g;
#pragma unroll
            for (int nt = 0; nt < 16; nt++){
                int col = nw*128 + nt*8 + tig*2;
                float bb0 = b1[e*FF + col], bb1 = b1[e*FF + col + 1];
                float a0 = d1[nt][0] + bb0, a1 = d1[nt][1] + bb1;
                float a2 = d1[nt][2] + bb0, a3 = d1[nt][3] + bb1;
                float v0 = 0.5f*a0*(1.f + erff(a0*0.70710678118654752440f));
                float v1 = 0.5f*a1*(1.f + erff(a1*0.70710678118654752440f));
                float v2 = 0.5f*a2*(1.f + erff(a2*0.70710678118654752440f));
                float v3 = 0.5f*a3*(1.f + erff(a3*0.70710678118654752440f));
                *(unsigned*)(smem + FSH + r0*528 + col*2)       = bf2(v0, v1);
                *(unsigned*)(smem + FSH + (r0+8)*528 + col*2)   = bf2(v2, v3);
            }
        }
        __syncthreads();

        // ---- GEMM2: eo = H @ W2t^T + b2 ; warp grid 2(M) x 4(N), tile 32x16 ----
        {
            int mw = wid & 1, nw = wid >> 1;
            float d2[2][2][4];
#pragma unroll
            for (int mt = 0; mt < 2; mt++)
#pragma unroll
                for (int nt = 0; nt < 2; nt++)
#pragma unroll
                    for (int q = 0; q < 4; q++) d2[mt][nt][q] = 0.f;
#pragma unroll
            for (int kt = 0; kt < 16; kt++){
                uint32_t a[2][4];
#pragma unroll
                for (int mt = 0; mt < 2; mt++)
                    ldm4(a[mt], sbm + FSH + (mw*32 + mt*16)*528 + kt*32 + aoffH);
#pragma unroll
                for (int nt = 0; nt < 2; nt++){
                    int brow = nw*16 + nt*8 + g;
                    uint32_t b[2];
                    b[0] = *(const uint32_t*)(smem + FSW2 + brow*528 + kt*32 + tig*4);
                    b[1] = *(const uint32_t*)(smem + FSW2 + brow*528 + kt*32 + tig*4 + 16);
#pragma unroll
                    for (int mt = 0; mt < 2; mt++)
                        mma16816(d2[mt][nt], a[mt], b);
                }
            }
#pragma unroll
            for (int mt = 0; mt < 2; mt++){
                int r = tok0 + mw*32 + mt*16 + g;
#pragma unroll
                for (int nt = 0; nt < 2; nt++){
                    int col = nw*16 + nt*8 + tig*2;
                    float bb0 = b2[e*DD + col], bb1 = b2[e*DD + col + 1];
                    *(float2*)(g_eo + ((size_t)r*EE + e)*DD + col) =
                        make_float2(d2[mt][nt][0] + bb0, d2[mt][nt][1] + bb1);
                    *(float2*)(g_eo + ((size_t)(r+8)*EE + e)*DD + col) =
                        make_float2(d2[mt][nt][2] + bb0, d2[mt][nt][3] + bb1);
                }
            }
        }
    }
}

// ---------------- K3: gates + gated sum + residual + LN -> bf16 hi/lo ----------------
// 8 lanes per token; 32 tokens per 256-thread block; grid 256.
__global__ __launch_bounds__(256) void k_combine(
    const float* __restrict__ Wg, const float* __restrict__ bg,
    const float* __restrict__ ln_g, const float* __restrict__ ln_b)
{
    __shared__ float sWg[DD*EE];
    __shared__ float sg[DD], sb[DD], sbg[EE];
    int tid = threadIdx.x;
    for (int i = tid; i < DD*EE; i += 256) sWg[i] = Wg[i];
    if (tid < DD){ sg[tid] = ln_g[tid]; sb[tid] = ln_b[tid]; }
    if (tid < EE) sbg[tid] = bg[tid];
    __syncthreads();

    int j  = tid & 7;                       // lane-in-token = expert id / d-octet
    int bt = blockIdx.x*32 + (tid >> 3);

    // gate logit for expert j
    float gl = sbg[j];
    const float4* mr = (const float4*)(g_mem + (size_t)bt*DD);
#pragma unroll
    for (int k4 = 0; k4 < 16; k4++){
        float4 m4 = mr[k4];
        gl += m4.x*sWg[(k4*4+0)*EE+j] + m4.y*sWg[(k4*4+1)*EE+j]
            + m4.z*sWg[(k4*4+2)*EE+j] + m4.w*sWg[(k4*4+3)*EE+j];
    }
    // softmax over the 8-lane group
    float mx = gl;
#pragma unroll
    for (int s = 1; s < 8; s <<= 1) mx = fmaxf(mx, __shfl_xor_sync(0xffffffffu, mx, s, 8));
    float ge = expf(gl - mx);
    float sum = ge;
#pragma unroll
    for (int s = 1; s < 8; s <<= 1) sum += __shfl_xor_sync(0xffffffffu, sum, s, 8);
    ge /= sum;

    // lane j owns d in [8j, 8j+8)
    float acc[8];
    {
        const float4* er = (const float4*)(g_emb + (size_t)bt*DD + 8*j);
        float4 v0 = er[0], v1 = er[1];
        acc[0]=v0.x; acc[1]=v0.y; acc[2]=v0.z; acc[3]=v0.w;
        acc[4]=v1.x; acc[5]=v1.y; acc[6]=v1.z; acc[7]=v1.w;
    }
#pragma unroll
    for (int e = 0; e < EE; e++){
        float w = __shfl_sync(0xffffffffu, ge, e, 8);
        const float4* eor = (const float4*)(g_eo + ((size_t)bt*EE + e)*DD + 8*j);
        float4 v0 = eor[0], v1 = eor[1];
        acc[0]+=w*v0.x; acc[1]+=w*v0.y; acc[2]+=w*v0.z; acc[3]+=w*v0.w;
        acc[4]+=w*v1.x; acc[5]+=w*v1.y; acc[6]+=w*v1.z; acc[7]+=w*v1.w;
    }
    float s1 = 0.f, s2 = 0.f;
#pragma unroll
    for (int i = 0; i < 8; i++){ s1 += acc[i]; s2 += acc[i]*acc[i]; }
#pragma unroll
    for (int s = 1; s < 8; s <<= 1){
        s1 += __shfl_xor_sync(0xffffffffu, s1, s, 8);
        s2 += __shfl_xor_sync(0xffffffffu, s2, s, 8);
    }
    float mu = s1 * (1.f/DD);
    float var = s2 * (1.f/DD) - mu*mu;
    float rs = rsqrtf(var + 1e-5f);

    unsigned hw[4], lw[4];
#pragma unroll
    for (int i = 0; i < 4; i++){
        float o0 = sg[8*j+2*i+0]*(acc[2*i+0]-mu)*rs + sb[8*j+2*i+0];
        float o1 = sg[8*j+2*i+1]*(acc[2*i+1]-mu)*rs + sb[8*j+2*i+1];
        float h0 = __bfloat162float(__float2bfloat16(o0));
        float h1 = __bfloat162float(__float2bfloat16(o1));
        hw[i] = bf2(h0, h1);
        lw[i] = bf2(o0 - h0, o1 - h1);
    }
    *(uint4*)(g_outh + (size_t)bt*DD + 8*j) = *(uint4*)hw;
    *(uint4*)(g_outl + (size_t)bt*DD + 8*j) = *(uint4*)lw;
}

// ---------------- K4: head GEMM, B-resident, 16 warps/CTA (HMMA bf16x3) ----------------
#define HM_STRIDE 144
#define HM_TILE   (128*HM_STRIDE)
#define SB_BHI    0
#define SB_BLO    HM_TILE
#define SB_A      (2*HM_TILE)
#define HM_TOTAL  (SB_A + 2*2*HM_TILE)
#define NMT 8

__global__ __launch_bounds__(512) void k_head_mma(
    const float* __restrict__ hb, float* __restrict__ out)
{
    extern __shared__ char smem[];
    uint32_t sbm = smem_u32(smem);
    int tid = threadIdx.x;
    int wid = tid >> 5, lane = tid & 31;
    int n0 = blockIdx.x * 128;
    int mt0 = blockIdx.y * NMT;

    int var  = (tid >> 7) & 1;
    int row  = tid & 127;
    int half = tid >> 8;

    {
        const __nv_bfloat16* src = (var ? g_hWl : g_hWh) + (size_t)(n0 + row)*DD + half*32;
        uint32_t dst = sbm + (var ? SB_BLO : SB_BHI) + row*HM_STRIDE + half*64;
#pragma unroll
        for (int j = 0; j < 4; j++) cpa16(dst + j*16, (const char*)src + j*16);
    }
    {
        const __nv_bfloat16* src = (var ? g_outl : g_outh) + (size_t)(mt0*128 + row)*DD + half*32;
        uint32_t dst = sbm + SB_A + var*HM_TILE + row*HM_STRIDE + half*64;
#pragma unroll
        for (int j = 0; j < 4; j++) cpa16(dst + j*16, (const char*)src + j*16);
    }
    cpa_commit();
    {
        const __nv_bfloat16* src = (var ? g_outl : g_outh) + (size_t)((mt0+1)*128 + row)*DD + half*32;
        uint32_t dst = sbm + SB_A + 2*HM_TILE + var*HM_TILE + row*HM_STRIDE + half*64;
#pragma unroll
        for (int j = 0; j < 4; j++) cpa16(dst + j*16, (const char*)src + j*16);
    }
    cpa_commit();

    int mw = wid & 3, nw = wid >> 2;
    int g = lane >> 2, tig = lane & 3;
    int lr = lane & 7, sel = lane >> 3;
    int a_lane_off = (lr + (sel & 1)*8)*HM_STRIDE + ((sel >> 1)*8)*2;

    float2 bv[4];
#pragma unroll
    for (int nt = 0; nt < 4; nt++)
        bv[nt] = *(const float2*)(hb + n0 + nw*32 + nt*8 + tig*2);

    for (int i = 0; i < NMT; i++){
        cpa_wait1();
        __syncthreads();

        float d[2][4][4];
#pragma unroll
        for (int mt = 0; mt < 2; mt++)
#pragma unroll
            for (int nt = 0; nt < 4; nt++)
#pragma unroll
                for (int q = 0; q < 4; q++) d[mt][nt][q] = 0.f;

        uint32_t abase = sbm + SB_A + (i & 1)*2*HM_TILE;
#pragma unroll
        for (int pass = 0; pass < 3; pass++){
            uint32_t Ab = abase + ((pass == 2) ? HM_TILE : 0);
            uint32_t Boff = (pass == 1) ? SB_BLO : SB_BHI;
#pragma unroll
            for (int kt = 0; kt < 4; kt++){
                int k0 = kt*16;
                uint32_t a[2][4];
#pragma unroll
                for (int mt = 0; mt < 2; mt++)
                    ldm4(a[mt], Ab + (mw*32 + mt*16)*HM_STRIDE + k0*2 + a_lane_off);
                uint32_t b[4][2];
#pragma unroll
                for (int nt = 0; nt < 4; nt++){
                    int boff = Boff + (nw*32 + nt*8 + g)*HM_STRIDE + (k0 + tig*2)*2;
                    b[nt][0] = *(const uint32_t*)(smem + boff);
                    b[nt][1] = *(const uint32_t*)(smem + boff + 16);
                }
#pragma unroll
                for (int mt = 0; mt < 2; mt++)
#pragma unroll
                    for (int nt = 0; nt < 4; nt++)
                        mma16816(d[mt][nt], a[mt], b[nt]);
            }
        }
        __syncthreads();

        if (i + 2 < NMT){
            const __nv_bfloat16* src = (var ? g_outl : g_outh)
                + (size_t)((mt0+i+2)*128 + row)*DD + half*32;
            uint32_t dst = sbm + SB_A + (i & 1)*2*HM_TILE + var*HM_TILE + row*HM_STRIDE + half*64;
#pragma unroll
            for (int j = 0; j < 4; j++) cpa16(dst + j*16, (const char*)src + j*16);
        }
        cpa_commit();

        int m0 = (mt0 + i) * 128;
#pragma unroll
        for (int mt = 0; mt < 2; mt++){
            int r = m0 + mw*32 + mt*16 + g;
#pragma unroll
            for (int nt = 0; nt < 4; nt++){
                int col = n0 + nw*32 + nt*8 + tig*2;
                *(float2*)(out + (size_t)r*VV + col) =
                    make_float2(d[mt][nt][0] + bv[nt].x, d[mt][nt][1] + bv[nt].y);
                *(float2*)(out + (size_t)(r + 8)*VV + col) =
                    make_float2(d[mt][nt][2] + bv[nt].x, d[mt][nt][3] + bv[nt].y);
            }
        }
    }
}

// ---------------- launch ----------------
extern "C" void kernel_launch(void* const* d_in, const int* in_sizes, int n_in,
                              void* d_out, int out_size)
{
    const int*   x     = (const int*)  d_in[0];
    const float* tab   = (const float*)d_in[1];
    const float* Wm    = (const float*)d_in[2];
    const float* Um    = (const float*)d_in[3];
    const float* bm    = (const float*)d_in[4];
    const float* Wg    = (const float*)d_in[5];
    const float* bg    = (const float*)d_in[6];
    const float* W1    = (const float*)d_in[7];
    const float* b1    = (const float*)d_in[8];
    const float* W2    = (const float*)d_in[9];
    const float* b2    = (const float*)d_in[10];
    const float* ln_g  = (const float*)d_in[11];
    const float* ln_b  = (const float*)d_in[12];
    const float* headW = (const float*)d_in[13];
    const float* headb = (const float*)d_in[14];
    float* out = (float*)d_out;

    k_cvt_w<<<VV/128, 256>>>(headW);
    k_cvt_ffn<<<dim3(EE, 2), 256>>>(W1, W2);
    k_embA<<<BT, DD>>>(x, tab, Wm, bm);
    cudaFuncSetAttribute(k_main, cudaFuncAttributeMaxDynamicSharedMemorySize, FTOT);
    k_main<<<BB + (BT/64)*EE, 256, FTOT>>>(Um, b1, b2);        // recurrence || HMMA FFN
    k_combine<<<BT/32, 256>>>(Wg, bg, ln_g, ln_b);
    cudaFuncSetAttribute(k_head_mma, cudaFuncAttributeMaxDynamicSharedMemorySize, HM_TOTAL);
    k_head_mma<<<dim3(VV/128, BT/(128*NMT)), 512, HM_TOTAL>>>(headb, out);
}